// round 14
// baseline (speedup 1.0000x reference)
#include <cuda_runtime.h>
#include <cstdint>

#define LL 50          // labels + stop + start
#define LP 64          // padded row
#define NB 512
#define TT 1024
#define STOPI 48
#define STARTI 49
#define NEGV (-10000.0f)

typedef unsigned long long u64;

// Scratch: Viterbi carry history, padded rows. hist row (b*TT + t) = vit after step t.
__device__ float g_hist[(size_t)NB * TT * LP];   // 134 MB
__device__ int   g_order[NB];

// ---------------------------------------------------------------------------
// Pre-kernel: LPT order (descending len, stable by index)
// ---------------------------------------------------------------------------
__global__ void order_kernel(const int* __restrict__ lens) {
    __shared__ int sl[NB];
    int i = threadIdx.x;
    sl[i] = lens[i];
    __syncthreads();
    int li = sl[i];
    int r = 0;
#pragma unroll 8
    for (int j = 0; j < NB; j++) {
        int lj = sl[j];
        r += (lj > li) || (lj == li && j < i);
    }
    g_order[r] = i;
}

// Monotonic bijection float -> uint32 (order-preserving, tie-exact)
__device__ __forceinline__ unsigned mono(float f) {
    unsigned u = __float_as_uint(f);
    return u ^ ((unsigned)(((int)u) >> 31) | 0x80000000u);
}

// Packed f32x2 add (sm_100+): elementwise IEEE add on a register pair.
__device__ __forceinline__ u64 add2(u64 a, u64 b) {
    u64 r; asm("add.rn.f32x2 %0, %1, %2;" : "=l"(r) : "l"(a), "l"(b)); return r;
}

// ---------------------------------------------------------------------------
// Main kernel: 128-thread blocks, TWO batches per block in LOCKSTEP.
//   half 0 = warps {0,1} (SMSP 0,1), half 1 = warps {2,3} (SMSP 2,3)
// One plain __syncthreads() (7-cyc floor) per step; both halves run to
// maxlen, the shorter half stops storing at its own len (vit frozen).
// ---------------------------------------------------------------------------
__global__ __launch_bounds__(128) void crf_kernel(
    const float* __restrict__ feats,
    const int*   __restrict__ lens,
    const float* __restrict__ trans,
    float*       __restrict__ out)
{
    __shared__ float  Ts[LL * LP];                    // transitions (shared by both halves)
    __shared__ float4 vit4[2][2][LP / 4];             // [half][buf]
    __shared__ __align__(16) float ring[2][16 * LP];  // backward hist prefetch ring
    __shared__ __align__(16) float lring[2][16 * LP]; // forward logit ring
    __shared__ int sP[2][LP];                         // frozen-region pointer map P*

    const int tid  = threadIdx.x;
    const int half = tid >> 6;                        // 0 or 1
    const int lt   = tid & 63;                        // local tid within half
    const int b    = g_order[blockIdx.x * 2 + half];
    const int len  = lens[b];
    const int lenO = lens[g_order[blockIdx.x * 2 + (half ^ 1)]];
    const int maxlen = (len > lenO) ? len : lenO;

    // Load transitions into shared (all 128 threads, padded with NEG)
    for (int idx = tid; idx < LL * LP; idx += 128) {
        int row = idx >> 6, f = idx & 63;
        Ts[idx] = (f < LL) ? trans[row * LL + f] : NEGV;
    }
    float* vs = (float*)&vit4[half][0];
    {
        int l = lt;
        vs[0 * LP + l] = (l == STARTI) ? 0.0f : NEGV;
        vs[1 * LP + l] = NEGV;                         // padding persists
    }

    const int to  = lt;
    const int toc = (to < LL) ? to : (LL - 1);
    const float* frow = feats + (size_t)b * TT * LL + toc;
    float*       hrow = g_hist + (size_t)b * TT * LP + to;

    // Prologue: logit cp.async ring, slots 0..7 (distance 8, depth 16)
    const uint32_t lrbase = (uint32_t)__cvta_generic_to_shared(&lring[half][0]);
    for (int k = 0; k < 8; k++) {
        int tc = k; if (tc > len - 1) tc = len - 1;
        const float* gp = frow + (size_t)tc * LL;
        uint32_t sa = lrbase + (((k & 15) * LP + lt) * 4);
        asm volatile("cp.async.ca.shared.global [%0], [%1], 4;\n" :: "r"(sa), "l"(gp));
        asm volatile("cp.async.commit_group;\n" ::: "memory");
    }
    __syncthreads();                                   // Ts + vit0 visible

    // This thread's transition row, packed as 26 f32x2 pairs
    u64 T2[26];
#pragma unroll
    for (int j = 0; j < 26; j++) T2[j] = ((const u64*)&Ts[toc * LP])[j];
    const float tstop = Ts[STOPI * LP + toc];

    int p = 0;
    for (int t = 0; t < maxlen; t++) {
        const ulonglong2* vb = (const ulonglong2*)&vit4[half][p][0];
        float m0 = -3.0e38f, m1 = m0, m2 = m0, m3 = m0;
        float m4 = m0, m5 = m0, m6 = m0, m7 = m0;      // 8 accumulators: chain 7-deep
#pragma unroll
        for (int j = 0; j < 13; j++) {
            ulonglong2 w = vb[j];                      // LDS.128 broadcast
            union { u64 u; float2 f; } s0, s1;
            s0.u = add2(w.x, T2[2 * j]);               // packed adds (FADD2)
            s1.u = add2(w.y, T2[2 * j + 1]);
            if (j & 1) {
                m4 = fmaxf(m4, s0.f.x);
                m5 = fmaxf(m5, s0.f.y);
                m6 = fmaxf(m6, s1.f.x);
                m7 = fmaxf(m7, s1.f.y);
            } else {
                m0 = fmaxf(m0, s0.f.x);
                m1 = fmaxf(m1, s0.f.y);
                m2 = fmaxf(m2, s1.f.x);
                m3 = fmaxf(m3, s1.f.y);
            }
        }
        float vt = fmaxf(fmaxf(fmaxf(m0, m1), fmaxf(m2, m3)),
                         fmaxf(fmaxf(m4, m5), fmaxf(m6, m7)));

        asm volatile("cp.async.wait_group 7;\n" ::: "memory");
        float logit = lring[half][(t & 15) * LP + lt];
        float vn = vt + logit;                         // same assoc. order as reference
        if (t == len - 1) vn += tstop;                 // stop transition at c==1
        if (t < len && to < LL) {                      // frozen past own len
            vs[(p ^ 1) * LP + to] = vn;
            hrow[(size_t)t * LP] = vn;                 // hist[t] = carry after step t
        }
        // prefetch logit for step t+8 into slot (t+8)&15
        {
            int tc = t + 8; if (tc > len - 1) tc = len - 1;
            const float* gp = frow + (size_t)tc * LL;
            uint32_t sa = lrbase + ((((t + 8) & 15) * LP + lt) * 4);
            asm volatile("cp.async.ca.shared.global [%0], [%1], 4;\n" :: "r"(sa), "l"(gp));
            asm volatile("cp.async.commit_group;\n" ::: "memory");
        }
        __syncthreads();
        p ^= 1;
    }
    asm volatile("cp.async.wait_group 0;\n" ::: "memory");  // drain logit groups

    // Final carry for THIS half lives in buffer (len & 1).
    float* vfin = &vs[(len & 1) * LP];

    // ---------------- Frozen pointer map P* (this half, once) ---------------
    {
        float best = -3.0e38f; int bi = 0;
#pragma unroll
        for (int j = 0; j < 26; j++) {
            union { u64 u; float2 f; } tt; tt.u = T2[j];
            float c0 = vfin[2 * j]     + tt.f.x;
            if (c0 > best) { best = c0; bi = 2 * j; }
            float c1 = vfin[2 * j + 1] + tt.f.y;
            if (c1 > best) { best = c1; bi = 2 * j + 1; }
        }
        if (to < LL) sP[half][to] = bi;                // first-tie == reference argmax
    }
    __syncthreads();

    // ---------------- Backward: first warp of this half only ----------------
    if (lt >= 32) return;
    const int f = lt;
    float* pout = out + NB + (size_t)b * TT;

    // scores / idx from final vit (exact max+first-argmax via monotonic keys)
    unsigned k1 = mono(vfin[f]);
    unsigned k2 = (f < LL - 32) ? mono(vfin[32 + f]) : 0u;
    unsigned wm = __reduce_max_sync(0xFFFFFFFFu, k1 > k2 ? k1 : k2);
    unsigned b1 = __ballot_sync(0xFFFFFFFFu, k1 == wm);
    unsigned b2 = __ballot_sync(0xFFFFFFFFu, (k2 == wm) && (f < LL - 32));
    int idx = b1 ? (__ffs(b1) - 1) : (31 + __ffs(b2));
    unsigned su = (wm & 0x80000000u) ? (wm ^ 0x80000000u) : ~wm;
    if (f == 0) {
        out[b] = __uint_as_float(su);                  // score
        pout[TT - 1] = (float)idx;                     // last path entry
    }

    int i = idx;

    // Frozen region: steps t in [len, 1023] all use P* (carry is frozen).
    if (len < TT) {
        int fh = len - 1, ii = i;
        if (f == 0) {
            int t = TT - 1, cur = i;
            for (; t >= len; --t) {
                int ni = sP[half][cur];
                pout[t - 1] = (float)ni;
                if (ni == cur) { --t; break; }         // fixed point: rest is constant
                cur = ni;
            }
            fh = t; ii = cur;
        }
        fh = __shfl_sync(0xFFFFFFFFu, fh, 0);
        i  = __shfl_sync(0xFFFFFFFFu, ii, 0);
        for (int t = fh - f; t >= len; t -= 32)        // parallel constant fill
            pout[t - 1] = (float)i;
    }

    // Real region: steps t = len-1 .. 1, recompute argmax from hist rows.
    const int S = len - 1;
    if (S > 0) {
        const float* hbase = g_hist + (size_t)b * TT * LP;
        uint32_t ring_base = (uint32_t)__cvta_generic_to_shared(&ring[half][0]);
        // step s looks at carry after step (len-2-s): hist row (len-2-s)
        for (int s = 0; s < 12; s++) {
            int k = len - 2 - s; if (k < 0) k = 0;
            if (f < 16) {
                const float* gp = hbase + (size_t)k * LP + f * 4;
                uint32_t sa = ring_base + (((s & 15) * LP + f * 4) * 4);
                asm volatile("cp.async.cg.shared.global [%0], [%1], 16;\n" :: "r"(sa), "l"(gp));
            }
            asm volatile("cp.async.commit_group;\n" ::: "memory");
        }
        for (int s = 0; s < S; s++) {
            int t = len - 1 - s;
            if (s + 12 >= S) { asm volatile("cp.async.wait_group 0;\n" ::: "memory"); }
            else            { asm volatile("cp.async.wait_group 11;\n" ::: "memory"); }
            __syncwarp();
            const float* rr = &ring[half][(s & 15) * LP];
            float c1 = rr[f]      + Ts[i * LP + f];
            float c2 = rr[32 + f] + Ts[i * LP + 32 + f];
            unsigned q1 = mono(c1);
            unsigned q2 = (f < LL - 32) ? mono(c2) : 0u;
            unsigned qm = __reduce_max_sync(0xFFFFFFFFu, q1 > q2 ? q1 : q2);
            unsigned a1 = __ballot_sync(0xFFFFFFFFu, q1 == qm);
            unsigned a2 = __ballot_sync(0xFFFFFFFFu, (q2 == qm) && (f < LL - 32));
            int ni = a1 ? (__ffs(a1) - 1) : (31 + __ffs(a2));
            if (f == 0) pout[t - 1] = (float)ni;
            i = ni;
            __syncwarp();
            int sp = s + 12;
            if (sp < S) {
                int k = len - 2 - sp;
                if (f < 16) {
                    const float* gp = hbase + (size_t)k * LP + f * 4;
                    uint32_t sa = ring_base + (((sp & 15) * LP + f * 4) * 4);
                    asm volatile("cp.async.cg.shared.global [%0], [%1], 16;\n" :: "r"(sa), "l"(gp));
                }
            }
            asm volatile("cp.async.commit_group;\n" ::: "memory");
        }
    }
}

extern "C" void kernel_launch(void* const* d_in, const int* in_sizes, int n_in,
                              void* d_out, int out_size) {
    const float* feats = (const float*)d_in[0];
    const int*   lens  = (const int*)d_in[1];
    const float* trans = (const float*)d_in[2];
    float* out = (float*)d_out;
    (void)in_sizes; (void)n_in; (void)out_size;

    order_kernel<<<1, NB>>>(lens);
    crf_kernel<<<NB / 2, 128>>>(feats, lens, trans, out);
}

// round 15
// speedup vs baseline: 1.1684x; 1.1684x over previous
#include <cuda_runtime.h>
#include <cstdint>

#define LL 50          // labels + stop + start
#define LP 64          // padded row
#define NB 512
#define TT 1024
#define STOPI 48
#define STARTI 49
#define NEGV (-10000.0f)

typedef unsigned long long u64;

// Scratch: Viterbi carry history, padded rows. hist row (b*TT + t) = vit after step t.
__device__ float g_hist[(size_t)NB * TT * LP];   // 134 MB
__device__ int   g_order[NB];

// ---------------------------------------------------------------------------
// Pre-kernel: LPT order (descending len, stable by index)
// ---------------------------------------------------------------------------
__global__ void order_kernel(const int* __restrict__ lens) {
    __shared__ int sl[NB];
    int i = threadIdx.x;
    sl[i] = lens[i];
    __syncthreads();
    int li = sl[i];
    int r = 0;
#pragma unroll 8
    for (int j = 0; j < NB; j++) {
        int lj = sl[j];
        r += (lj > li) || (lj == li && j < i);
    }
    g_order[r] = i;
}

// Monotonic bijection float -> uint32 (order-preserving, tie-exact)
__device__ __forceinline__ unsigned mono(float f) {
    unsigned u = __float_as_uint(f);
    return u ^ ((unsigned)(((int)u) >> 31) | 0x80000000u);
}

// Packed f32x2 add (sm_100+): elementwise IEEE add on a register pair.
__device__ __forceinline__ u64 add2(u64 a, u64 b) {
    u64 r; asm("add.rn.f32x2 %0, %1, %2;" : "=l"(r) : "l"(a), "l"(b)); return r;
}

// ---------------------------------------------------------------------------
// Main kernel: one block (64 threads = 2 warps) per batch element (R10 layout).
// Forward: thread `to` computes max over `from`; adds packed (FADD2), maxes
//          scalar (FMNMX, 8 accumulators); logits streamed via cp.async ring.
// Backward: frozen-region pointers via precomputed map P* with fixed-point
//           early exit; real region recomputed with a cp.async hist ring.
// ---------------------------------------------------------------------------
__global__ __launch_bounds__(64) void crf_kernel(
    const float* __restrict__ feats,
    const int*   __restrict__ lens,
    const float* __restrict__ trans,
    float*       __restrict__ out)
{
    __shared__ float  Ts[LL * LP];                    // transitions, padded cols = NEG
    __shared__ float4 vit4[2][LP / 4];                // double-buffered vit
    __shared__ __align__(16) float ring[16 * LP];     // backward hist prefetch ring
    __shared__ __align__(16) float lring[16 * LP];    // forward logit ring
    __shared__ int sP[LP];                            // frozen-region pointer map P*

    const int tid = threadIdx.x;
    const int b   = g_order[blockIdx.x];
    const int len = lens[b];

    // Load transitions into shared (padded with NEG)
    for (int idx = tid; idx < LL * LP; idx += 64) {
        int row = idx >> 6, f = idx & 63;
        Ts[idx] = (f < LL) ? trans[row * LL + f] : NEGV;
    }
    float* vs = (float*)vit4;
    {
        int l = tid;
        vs[0 * LP + l] = (l == STARTI) ? 0.0f : NEGV;
        vs[1 * LP + l] = NEGV;                         // padding persists
    }

    const int to  = tid;
    const int toc = (to < LL) ? to : (LL - 1);
    const float* frow = feats + (size_t)b * TT * LL + toc;
    float*       hrow = g_hist + (size_t)b * TT * LP + to;

    // Prologue: logit cp.async ring, slots 0..7 (distance 8, depth 16)
    const uint32_t lrbase = (uint32_t)__cvta_generic_to_shared(lring);
    for (int k = 0; k < 8; k++) {
        int tc = k; if (tc > len - 1) tc = len - 1;
        const float* gp = frow + (size_t)tc * LL;
        uint32_t sa = lrbase + (((k & 15) * LP + tid) * 4);
        asm volatile("cp.async.ca.shared.global [%0], [%1], 4;\n" :: "r"(sa), "l"(gp));
        asm volatile("cp.async.commit_group;\n" ::: "memory");
    }
    __syncthreads();

    // This thread's transition row, packed as 25 f32x2 pairs (from 0..49 only)
    u64 T2[25];
#pragma unroll
    for (int j = 0; j < 25; j++) T2[j] = ((const u64*)&Ts[toc * LP])[j];
    const float tstop = Ts[STOPI * LP + toc];

    int p = 0;
    for (int t = 0; t < len; t++) {
        // Logit first: prefetched >=8 steps ago, off the dependence chain tail.
        asm volatile("cp.async.wait_group 7;\n" ::: "memory");
        float logit = lring[(t & 15) * LP + tid];

        const ulonglong2* vb = (const ulonglong2*)&vit4[p][0];
        float m0 = -3.0e38f, m1 = m0, m2 = m0, m3 = m0;
        float m4 = m0, m5 = m0, m6 = m0, m7 = m0;      // 8 accumulators: chain ~6 deep
#pragma unroll
        for (int j = 0; j < 12; j++) {                 // pairs 0..23 (from 0..47)
            ulonglong2 w = vb[j];                      // LDS.128 broadcast
            union { u64 u; float2 f; } s0, s1;
            s0.u = add2(w.x, T2[2 * j]);               // packed adds (FADD2)
            s1.u = add2(w.y, T2[2 * j + 1]);
            if (j & 1) {
                m4 = fmaxf(m4, s0.f.x);
                m5 = fmaxf(m5, s0.f.y);
                m6 = fmaxf(m6, s1.f.x);
                m7 = fmaxf(m7, s1.f.y);
            } else {
                m0 = fmaxf(m0, s0.f.x);
                m1 = fmaxf(m1, s0.f.y);
                m2 = fmaxf(m2, s1.f.x);
                m3 = fmaxf(m3, s1.f.y);
            }
        }
        {                                              // pair 24 (from 48..49)
            union { u64 u; float2 f; } s;
            s.u = add2(((const u64*)vb)[24], T2[24]);
            m0 = fmaxf(m0, s.f.x);
            m1 = fmaxf(m1, s.f.y);
        }
        float vt = fmaxf(fmaxf(fmaxf(m0, m1), fmaxf(m2, m3)),
                         fmaxf(fmaxf(m4, m5), fmaxf(m6, m7)));

        float vn = vt + logit;                         // same assoc. order as reference
        if (t == len - 1) vn += tstop;                 // stop transition at c==1
        if (to < LL) {
            vs[(p ^ 1) * LP + to] = vn;
            hrow[(size_t)t * LP] = vn;                 // hist[t] = carry after step t
        }
        // prefetch logit for step t+8 into slot (t+8)&15
        {
            int tc = t + 8; if (tc > len - 1) tc = len - 1;
            const float* gp = frow + (size_t)tc * LL;
            uint32_t sa = lrbase + ((((t + 8) & 15) * LP + tid) * 4);
            asm volatile("cp.async.ca.shared.global [%0], [%1], 4;\n" :: "r"(sa), "l"(gp));
            asm volatile("cp.async.commit_group;\n" ::: "memory");
        }
        __syncthreads();
        p ^= 1;
    }
    asm volatile("cp.async.wait_group 0;\n" ::: "memory");  // drain logit groups

    // ---------------- Frozen pointer map P* (all threads, once) -------------
    float* vfin = &vs[p * LP];
    {
        float best = -3.0e38f; int bi = 0;
#pragma unroll
        for (int j = 0; j < 25; j++) {
            union { u64 u; float2 f; } tt; tt.u = T2[j];
            float c0 = vfin[2 * j]     + tt.f.x;
            if (c0 > best) { best = c0; bi = 2 * j; }
            float c1 = vfin[2 * j + 1] + tt.f.y;
            if (c1 > best) { best = c1; bi = 2 * j + 1; }
        }
        if (to < LL) sP[to] = bi;                      // first-tie == reference argmax
    }
    __syncthreads();

    // ---------------- Backward: warp 0 only ----------------
    if (tid >= 32) return;
    const int f = tid;
    float* pout = out + NB + (size_t)b * TT;

    // scores / idx from final vit (exact max+first-argmax via monotonic keys)
    unsigned k1 = mono(vfin[f]);
    unsigned k2 = (f < LL - 32) ? mono(vfin[32 + f]) : 0u;
    unsigned wm = __reduce_max_sync(0xFFFFFFFFu, k1 > k2 ? k1 : k2);
    unsigned b1 = __ballot_sync(0xFFFFFFFFu, k1 == wm);
    unsigned b2 = __ballot_sync(0xFFFFFFFFu, (k2 == wm) && (f < LL - 32));
    int idx = b1 ? (__ffs(b1) - 1) : (31 + __ffs(b2));
    unsigned su = (wm & 0x80000000u) ? (wm ^ 0x80000000u) : ~wm;
    if (f == 0) {
        out[b] = __uint_as_float(su);                  // score
        pout[TT - 1] = (float)idx;                     // last path entry
    }

    int i = idx;

    // Frozen region: steps t in [len, 1023] all use P* (carry is frozen).
    if (len < TT) {
        int fh = len - 1, ii = i;
        if (f == 0) {
            int t = TT - 1, cur = i;
            for (; t >= len; --t) {
                int ni = sP[cur];
                pout[t - 1] = (float)ni;
                if (ni == cur) { --t; break; }         // fixed point: rest is constant
                cur = ni;
            }
            fh = t; ii = cur;
        }
        fh = __shfl_sync(0xFFFFFFFFu, fh, 0);
        i  = __shfl_sync(0xFFFFFFFFu, ii, 0);
        for (int t = fh - f; t >= len; t -= 32)        // parallel constant fill
            pout[t - 1] = (float)i;
    }

    // Real region: steps t = len-1 .. 1, recompute argmax from hist rows.
    const int S = len - 1;
    if (S > 0) {
        const float* hbase = g_hist + (size_t)b * TT * LP;
        uint32_t ring_base = (uint32_t)__cvta_generic_to_shared(ring);
        // step s looks at carry after step (len-2-s): hist row (len-2-s)
        for (int s = 0; s < 12; s++) {
            int k = len - 2 - s; if (k < 0) k = 0;
            if (f < 16) {
                const float* gp = hbase + (size_t)k * LP + f * 4;
                uint32_t sa = ring_base + (((s & 15) * LP + f * 4) * 4);
                asm volatile("cp.async.cg.shared.global [%0], [%1], 16;\n" :: "r"(sa), "l"(gp));
            }
            asm volatile("cp.async.commit_group;\n" ::: "memory");
        }
        for (int s = 0; s < S; s++) {
            int t = len - 1 - s;
            if (s + 12 >= S) { asm volatile("cp.async.wait_group 0;\n" ::: "memory"); }
            else            { asm volatile("cp.async.wait_group 11;\n" ::: "memory"); }
            __syncwarp();
            const float* rr = &ring[(s & 15) * LP];
            float c1 = rr[f]      + Ts[i * LP + f];
            float c2 = rr[32 + f] + Ts[i * LP + 32 + f];
            unsigned q1 = mono(c1);
            unsigned q2 = (f < LL - 32) ? mono(c2) : 0u;
            unsigned qm = __reduce_max_sync(0xFFFFFFFFu, q1 > q2 ? q1 : q2);
            unsigned a1 = __ballot_sync(0xFFFFFFFFu, q1 == qm);
            unsigned a2 = __ballot_sync(0xFFFFFFFFu, (q2 == qm) && (f < LL - 32));
            int ni = a1 ? (__ffs(a1) - 1) : (31 + __ffs(a2));
            if (f == 0) pout[t - 1] = (float)ni;
            i = ni;
            __syncwarp();
            int sp = s + 12;
            if (sp < S) {
                int k = len - 2 - sp;
                if (f < 16) {
                    const float* gp = hbase + (size_t)k * LP + f * 4;
                    uint32_t sa = ring_base + (((sp & 15) * LP + f * 4) * 4);
                    asm volatile("cp.async.cg.shared.global [%0], [%1], 16;\n" :: "r"(sa), "l"(gp));
                }
            }
            asm volatile("cp.async.commit_group;\n" ::: "memory");
        }
    }
}

extern "C" void kernel_launch(void* const* d_in, const int* in_sizes, int n_in,
                              void* d_out, int out_size) {
    const float* feats = (const float*)d_in[0];
    const int*   lens  = (const int*)d_in[1];
    const float* trans = (const float*)d_in[2];
    float* out = (float*)d_out;
    (void)in_sizes; (void)n_in; (void)out_size;

    order_kernel<<<1, NB>>>(lens);
    crf_kernel<<<NB, 64>>>(feats, lens, trans, out);
}